// round 14
// baseline (speedup 1.0000x reference)
#include <cuda_runtime.h>
#include <cuda_fp16.h>
#include <cstdint>

// TrajectoryGRU: warp-specialized fp16 single-pass mma, NT=768.
// Warps 0-7 (M) = HMMA, all A-frags from SMEM. Warps 8-23 (C) = gi +
// activations + w2; C-thread = (j, n0) -> 4 n's of one j.
// Two 16-row halves pipelined, 2 named barriers/step. Grid 512.

#define NT 768
#define OFF_WA  0        // W_hh A-frags [jt8][g3][kc8][l32] u4 = 98304
#define OFF_W1F 98304    // w1 A-frags [jt8][kc8][l32] u4 = 32768
#define OFF_HF  131072   // [h2][slot128 x 8B] = 8192
#define OFF_DG  139264   // [h2][3*16*132] f32 = 50688
#define OFF_AT  189952   // [h2][16*132] f32 = 16896
#define OFF_XSE 206848   // [h2][par2][96] f32 = 1536
#define OFF_XSD 208384   // [h2][96] f32 = 768
#define OFF_W2  209152   // [6][128] f32 = 3072
#define SMEM_TOTAL 212224

__device__ __forceinline__ void mma16816(float* d, const uint32_t* a,
                                         uint32_t b0, uint32_t b1) {
  asm volatile(
    "mma.sync.aligned.m16n8k16.row.col.f32.f16.f16.f32 "
    "{%0,%1,%2,%3}, {%4,%5,%6,%7}, {%8,%9}, {%0,%1,%2,%3};"
    : "+f"(d[0]), "+f"(d[1]), "+f"(d[2]), "+f"(d[3])
    : "r"(a[0]), "r"(a[1]), "r"(a[2]), "r"(a[3]), "r"(b0), "r"(b1));
}
__device__ __forceinline__ uint32_t packh2(float2 v) {
  __half2 p(__float2half_rn(v.x), __float2half_rn(v.y));
  return *reinterpret_cast<uint32_t*>(&p);
}
__device__ __forceinline__ float sigf(float v) {
  return __fdividef(1.0f, 1.0f + __expf(-v));
}
__device__ __forceinline__ float tanhfast(float v) {
  float av = fabsf(v), e = __expf(-2.0f * av);
  return copysignf(__fdividef(1.0f - e, 1.0f + e), v);
}
#define BARX(id, n) asm volatile("bar.sync %0, %1;" :: "r"(id), "r"(n) : "memory")

__global__ void __launch_bounds__(NT, 1)
gru_ws2_kernel(const float* __restrict__ history, const float* __restrict__ w_ih,
               const float* __restrict__ w_hh, const float* __restrict__ b_ih,
               const float* __restrict__ b_hh, const float* __restrict__ w1,
               const float* __restrict__ b1, const float* __restrict__ w2,
               const float* __restrict__ b2, float* __restrict__ out)
{
  extern __shared__ char sb[];
  const int tid = threadIdx.x, w = tid >> 5, l = tid & 31;
  const int grp = l >> 2, tg = l & 3;
  const int row0 = blockIdx.x * 32;
  const bool isM = w < 8;

  // ---------- cooperative init ----------
  for (int idx = tid; idx < 6144; idx += NT) {   // W_hh frags [jt][g][kc][l]
    int ll = idx & 31, kc = (idx >> 5) & 7, g = (idx >> 8) % 3, jt = idx / 768;
    int jA = jt * 16 + (ll >> 2), jB = jA + 8, k0 = kc * 16 + (ll & 3) * 2;
    const float* base = w_hh + (size_t)(g * 128) * 128;
    uint4 f = { packh2(*(const float2*)(base + (size_t)jA * 128 + k0)),
                packh2(*(const float2*)(base + (size_t)jB * 128 + k0)),
                packh2(*(const float2*)(base + (size_t)jA * 128 + k0 + 8)),
                packh2(*(const float2*)(base + (size_t)jB * 128 + k0 + 8)) };
    *(uint4*)(sb + OFF_WA + (size_t)idx * 16) = f;
  }
  for (int idx = tid; idx < 2048; idx += NT) {   // w1 frags [jt][kc][l]
    int ll = idx & 31, kc = (idx >> 5) & 7, jt = idx >> 8;
    int jA = jt * 16 + (ll >> 2), jB = jA + 8, k0 = kc * 16 + (ll & 3) * 2;
    uint4 f = { packh2(*(const float2*)(w1 + (size_t)jA * 128 + k0)),
                packh2(*(const float2*)(w1 + (size_t)jB * 128 + k0)),
                packh2(*(const float2*)(w1 + (size_t)jA * 128 + k0 + 8)),
                packh2(*(const float2*)(w1 + (size_t)jB * 128 + k0 + 8)) };
    *(uint4*)(sb + OFF_W1F + (size_t)idx * 16) = f;
  }
  for (int i = tid; i < 768; i += NT) ((float*)(sb + OFF_W2))[i] = w2[i];
  for (int i = tid; i < 2048; i += NT) ((uint32_t*)(sb + OFF_HF))[i] = 0u;
  if (tid < 192) {   // x(0) both halves, parity 0
    int hh = tid / 96, idx = tid - hh * 96, n = idx / 6, i = idx - n * 6;
    ((float*)(sb + OFF_XSE))[hh * 192 + idx] =
        history[(size_t)(row0 + hh * 16 + n) * 300 + i];
  }
  __syncthreads();

  if (isM) {
    // ================= M-warps: all HMMA =================
    const int jt = w;
    const int jA = jt * 16 + grp, jB = jA + 8;
    const float b1A = b1[jA], b1B = b1[jB];
    for (int t = 0; t <= 80; t++) {
      const bool doG = t < 80, doH = t > 50;
      #pragma unroll 1
      for (int h = 0; h < 2; h++) {
        float D[3][2][4], Da[2][4];
        #pragma unroll
        for (int g = 0; g < 3; g++)
          #pragma unroll
          for (int nt = 0; nt < 2; nt++)
            #pragma unroll
            for (int r = 0; r < 4; r++) D[g][nt][r] = 0.f;
        #pragma unroll
        for (int nt = 0; nt < 2; nt++)
          #pragma unroll
          for (int r = 0; r < 4; r++) Da[nt][r] = 0.f;
        const char* hfb = sb + OFF_HF + h * 4096;
        #pragma unroll
        for (int kc = 0; kc < 8; kc++) {
          uint2 v0 = *(const uint2*)(hfb + ((kc * 2 + 0) * 32 + l) * 8);
          uint2 v1 = *(const uint2*)(hfb + ((kc * 2 + 1) * 32 + l) * 8);
          if (doG) {
            #pragma unroll
            for (int g = 0; g < 3; g++) {
              uint4 a = *(const uint4*)(sb + OFF_WA +
                         ((size_t)((jt * 3 + g) * 8 + kc) * 32 + l) * 16);
              uint32_t A[4] = { a.x, a.y, a.z, a.w };
              mma16816(D[g][0], A, v0.x, v0.y);
              mma16816(D[g][1], A, v1.x, v1.y);
            }
          }
          if (doH) {
            uint4 a = *(const uint4*)(sb + OFF_W1F +
                       ((size_t)(jt * 8 + kc) * 32 + l) * 16);
            uint32_t A[4] = { a.x, a.y, a.z, a.w };
            mma16816(Da[0], A, v0.x, v0.y);
            mma16816(Da[1], A, v1.x, v1.y);
          }
        }
        if (doG) {
          float* dg = (float*)(sb + OFF_DG) + h * 6336;
          #pragma unroll
          for (int g = 0; g < 3; g++)
            #pragma unroll
            for (int nt = 0; nt < 2; nt++)
              #pragma unroll
              for (int rh = 0; rh < 2; rh++)
                #pragma unroll
                for (int cc = 0; cc < 2; cc++)
                  dg[(g * 16 + nt * 8 + tg * 2 + cc) * 132 + jt * 16 + rh * 8 + grp]
                      = D[g][nt][rh * 2 + cc];
        }
        if (doH) {
          float* at = (float*)(sb + OFF_AT) + h * 2112;
          #pragma unroll
          for (int nt = 0; nt < 2; nt++)
            #pragma unroll
            for (int rh = 0; rh < 2; rh++)
              #pragma unroll
              for (int cc = 0; cc < 2; cc++)
                at[(nt * 8 + tg * 2 + cc) * 132 + jt * 16 + rh * 8 + grp] =
                    fmaxf(Da[nt][rh * 2 + cc] + (rh ? b1B : b1A), 0.f);
        }
        BARX(h + 1, NT);
      }
    }
  } else {
    // ================= C-warps: gi + activations + epilogue =================
    const int c = tid - 256;            // 0..511
    const int j = c & 127, n0 = c >> 7; // thread owns j, rows n0*4..n0*4+3
    float wr[6], wz[6], wn[6];
    #pragma unroll
    for (int i = 0; i < 6; i++) {
      wr[i] = w_ih[(size_t)j * 6 + i];
      wz[i] = w_ih[(size_t)(128 + j) * 6 + i];
      wn[i] = w_ih[(size_t)(256 + j) * 6 + i];
    }
    const float br  = b_ih[j] + b_hh[j];
    const float bz  = b_ih[128 + j] + b_hh[128 + j];
    const float bin = b_ih[256 + j];
    const float bhn = b_hh[256 + j];
    float b2r = 0.f;
    if (c < 96) b2r = b2[c % 6];
    float hreg[2][4];
    #pragma unroll
    for (int h = 0; h < 2; h++)
      #pragma unroll
      for (int q = 0; q < 4; q++) hreg[h][q] = 0.f;
    // HF write offsets (j-dependent)
    const uint32_t sj = (uint32_t)((j >> 4) * 64 + ((j & 7) >> 1));
    const uint32_t bj = (uint32_t)(((j >> 3) & 1) * 4 + (j & 1) * 2);

    for (int t = 0; t <= 80; t++) {
      #pragma unroll 1
      for (int h = 0; h < 2; h++) {
        BARX(h + 1, NT);
        if (t > 50) {   // w2 epilogue for this half
          if (c < 96) {
            int n = c / 6, i = c - n * 6;
            const float4* a4 = (const float4*)((float*)(sb + OFF_AT)
                                + h * 2112 + n * 132);
            const float4* wv = (const float4*)((float*)(sb + OFF_W2) + i * 128);
            float acc = b2r;
            #pragma unroll 8
            for (int k4 = 0; k4 < 32; k4++) {
              float4 a = a4[k4], ww = wv[k4];
              acc = fmaf(a.x, ww.x, fmaf(a.y, ww.y,
                    fmaf(a.z, ww.z, fmaf(a.w, ww.w, acc))));
            }
            ((float*)(sb + OFF_XSD))[h * 96 + c] = acc;
            out[(size_t)(row0 + h * 16 + n) * 180 + (size_t)(t - 51) * 6 + i] = acc;
          }
          BARX(3, 512);   // C-only: xsd visible
        }
        if (t < 80) {     // gi + combine -> h_t
          const float* xq =
              (t < 50) ? (const float*)(sb + OFF_XSE) + (h * 2 + (t & 1)) * 96
            : (t == 50) ? (const float*)(sb + OFF_XSE) + (h * 2 + 1) * 96
            : (const float*)(sb + OFF_XSD) + h * 96;
          const float* dg = (const float*)(sb + OFF_DG) + h * 6336;
          #pragma unroll
          for (int q = 0; q < 4; q++) {
            const int n = n0 * 4 + q;
            const float* xp = xq + n * 6;        // warp-broadcast
            float gr = br, gz = bz, gn = bin;
            #pragma unroll
            for (int i = 0; i < 6; i++) {
              float xv = xp[i];
              gr = fmaf(wr[i], xv, gr);
              gz = fmaf(wz[i], xv, gz);
              gn = fmaf(wn[i], xv, gn);
            }
            float Dr = dg[(0 * 16 + n) * 132 + j];
            float Dz = dg[(1 * 16 + n) * 132 + j];
            float Dn = dg[(2 * 16 + n) * 132 + j];
            float r  = sigf(gr + Dr);
            float z  = sigf(gz + Dz);
            float nn = tanhfast(fmaf(r, Dn + bhn, gn));
            float hv = fmaf(z, hreg[h][q] - nn, nn);
            hreg[h][q] = hv;
            uint32_t slot = sj + (uint32_t)((n >> 3) * 32 + (n & 7) * 4);
            *(__half*)(sb + OFF_HF + h * 4096 + slot * 8 + bj)
                = __float2half_rn(hv);
          }
        }
        if (h == 1 && t + 1 < 50 && c < 192) {   // encoder x prefetch
          int hh = c / 96, idx = c - hh * 96, n = idx / 6, i = idx - n * 6;
          ((float*)(sb + OFF_XSE))[(hh * 2 + ((t + 1) & 1)) * 96 + idx] =
              history[(size_t)(row0 + hh * 16 + n) * 300 + (size_t)(t + 1) * 6 + i];
        }
      }
    }
  }
}

extern "C" void kernel_launch(void* const* d_in, const int* in_sizes, int n_in,
                              void* d_out, int out_size) {
  const float* history = (const float*)d_in[0];
  const float* w_ih    = (const float*)d_in[1];
  const float* w_hh    = (const float*)d_in[2];
  const float* b_ih    = (const float*)d_in[3];
  const float* b_hh    = (const float*)d_in[4];
  const float* w1      = (const float*)d_in[5];
  const float* b1      = (const float*)d_in[6];
  const float* w2      = (const float*)d_in[7];
  const float* b2      = (const float*)d_in[8];
  float* out = (float*)d_out;

  cudaFuncSetAttribute(gru_ws2_kernel,
                       cudaFuncAttributeMaxDynamicSharedMemorySize, SMEM_TOTAL);
  gru_ws2_kernel<<<512, NT, SMEM_TOTAL>>>(
      history, w_ih, w_hh, b_ih, b_hh, w1, b1, w2, b2, out);
}

// round 15
// speedup vs baseline: 1.1327x; 1.1327x over previous
#include <cuda_runtime.h>
#include <cuda_fp16.h>
#include <cstdint>

// TrajectoryGRU: WS fp16 mma, ROWS=64/CTA (grid=256 -> 2 waves).
// NT=512: warps 0-7 (M) = HMMA, r/z A-frags in regs, n/w1 from smem.
// Warps 8-15 (C) = gi + activations + w2. Two 32-row halves pipelined.

#define NT 512
#define OFF_WN  0        // n-gate A-frags [jt8][kc8][l32] u4 = 32768
#define OFF_W1F 32768    // w1 A-frags = 32768
#define OFF_HF  65536    // [h2][kc8][nt4][l32] u2 = 16384
#define OFF_DG  81920    // [h2][3][32][132] f32 = 101376
#define OFF_AT  183296   // [h2][32][132] f32 = 33792
#define OFF_XSE 217088   // [h2][par2][192] f32 = 3072
#define OFF_XSD 220160   // [h2][192] f32 = 1536
#define OFF_W2  221696   // [6][128] f32 = 3072
#define SMEM_TOTAL 224768

__device__ __forceinline__ void mma16816(float* d, const uint32_t* a,
                                         uint32_t b0, uint32_t b1) {
  asm volatile(
    "mma.sync.aligned.m16n8k16.row.col.f32.f16.f16.f32 "
    "{%0,%1,%2,%3}, {%4,%5,%6,%7}, {%8,%9}, {%0,%1,%2,%3};"
    : "+f"(d[0]), "+f"(d[1]), "+f"(d[2]), "+f"(d[3])
    : "r"(a[0]), "r"(a[1]), "r"(a[2]), "r"(a[3]), "r"(b0), "r"(b1));
}
__device__ __forceinline__ uint32_t packh2(float2 v) {
  __half2 p(__float2half_rn(v.x), __float2half_rn(v.y));
  return *reinterpret_cast<uint32_t*>(&p);
}
__device__ __forceinline__ float sigf(float v) {
  return __fdividef(1.0f, 1.0f + __expf(-v));
}
__device__ __forceinline__ float tanhfast(float v) {
  float av = fabsf(v), e = __expf(-2.0f * av);
  return copysignf(__fdividef(1.0f - e, 1.0f + e), v);
}
#define BARX(id, n) asm volatile("bar.sync %0, %1;" :: "r"(id), "r"(n) : "memory")

__global__ void __launch_bounds__(NT, 1)
gru_r64_kernel(const float* __restrict__ history, const float* __restrict__ w_ih,
               const float* __restrict__ w_hh, const float* __restrict__ b_ih,
               const float* __restrict__ b_hh, const float* __restrict__ w1,
               const float* __restrict__ b1, const float* __restrict__ w2,
               const float* __restrict__ b2, float* __restrict__ out)
{
  extern __shared__ char sb[];
  const int tid = threadIdx.x, w = tid >> 5, l = tid & 31;
  const int grp = l >> 2, tg = l & 3;
  const int row0 = blockIdx.x * 64;
  const bool isM = w < 8;

  // ---------- cooperative init ----------
  for (int idx = tid; idx < 2048; idx += NT) {   // n-gate frags [jt][kc][l]
    int ll = idx & 31, kc = (idx >> 5) & 7, jt = idx >> 8;
    int jA = jt * 16 + (ll >> 2), jB = jA + 8, k0 = kc * 16 + (ll & 3) * 2;
    const float* bn = w_hh + (size_t)(2 * 128) * 128;
    uint4 f = { packh2(*(const float2*)(bn + (size_t)jA * 128 + k0)),
                packh2(*(const float2*)(bn + (size_t)jB * 128 + k0)),
                packh2(*(const float2*)(bn + (size_t)jA * 128 + k0 + 8)),
                packh2(*(const float2*)(bn + (size_t)jB * 128 + k0 + 8)) };
    *(uint4*)(sb + OFF_WN + (size_t)idx * 16) = f;
  }
  for (int idx = tid; idx < 2048; idx += NT) {   // w1 frags
    int ll = idx & 31, kc = (idx >> 5) & 7, jt = idx >> 8;
    int jA = jt * 16 + (ll >> 2), jB = jA + 8, k0 = kc * 16 + (ll & 3) * 2;
    uint4 f = { packh2(*(const float2*)(w1 + (size_t)jA * 128 + k0)),
                packh2(*(const float2*)(w1 + (size_t)jB * 128 + k0)),
                packh2(*(const float2*)(w1 + (size_t)jA * 128 + k0 + 8)),
                packh2(*(const float2*)(w1 + (size_t)jB * 128 + k0 + 8)) };
    *(uint4*)(sb + OFF_W1F + (size_t)idx * 16) = f;
  }
  for (int i = tid; i < 768; i += NT) ((float*)(sb + OFF_W2))[i] = w2[i];
  for (int i = tid; i < 4096; i += NT) ((uint32_t*)(sb + OFF_HF))[i] = 0u;
  if (tid < 384) {   // x(0), parity 0, both halves
    int hh = tid / 192, r = (tid % 192) / 6, i = tid % 6;
    ((float*)(sb + OFF_XSE))[hh * 384 + r * 6 + i] =
        history[(size_t)(row0 + hh * 32 + r) * 300 + i];
  }
  __syncthreads();

  if (isM) {
    // ================= M-warps =================
    const int jt = w, jA = jt * 16 + grp, jB = jA + 8;
    const float b1A = b1[jA], b1B = b1[jB];
    uint32_t Ar[8][4], Az[8][4];
    #pragma unroll
    for (int kc = 0; kc < 8; kc++) {
      int k0 = kc * 16 + tg * 2;
      Ar[kc][0] = packh2(*(const float2*)(w_hh + (size_t)jA * 128 + k0));
      Ar[kc][1] = packh2(*(const float2*)(w_hh + (size_t)jB * 128 + k0));
      Ar[kc][2] = packh2(*(const float2*)(w_hh + (size_t)jA * 128 + k0 + 8));
      Ar[kc][3] = packh2(*(const float2*)(w_hh + (size_t)jB * 128 + k0 + 8));
      Az[kc][0] = packh2(*(const float2*)(w_hh + (size_t)(128 + jA) * 128 + k0));
      Az[kc][1] = packh2(*(const float2*)(w_hh + (size_t)(128 + jB) * 128 + k0));
      Az[kc][2] = packh2(*(const float2*)(w_hh + (size_t)(128 + jA) * 128 + k0 + 8));
      Az[kc][3] = packh2(*(const float2*)(w_hh + (size_t)(128 + jB) * 128 + k0 + 8));
    }
    for (int t = 0; t <= 80; t++) {
      const bool doG = t < 80, doH = t > 50;
      #pragma unroll 1
      for (int h = 0; h < 2; h++) {
        const char* hfb = sb + OFF_HF + h * 8192;
        float* dgh = (float*)(sb + OFF_DG) + h * 12672;
        float* ath = (float*)(sb + OFF_AT) + h * 4224;
        #pragma unroll
        for (int np = 0; np < 2; np++) {   // n-tile pairs: nt = np*2 + s
          float D[3][2][4], Da[2][4];
          #pragma unroll
          for (int g = 0; g < 3; g++)
            #pragma unroll
            for (int s = 0; s < 2; s++)
              #pragma unroll
              for (int r = 0; r < 4; r++) D[g][s][r] = 0.f;
          #pragma unroll
          for (int s = 0; s < 2; s++)
            #pragma unroll
            for (int r = 0; r < 4; r++) Da[s][r] = 0.f;
          #pragma unroll
          for (int kc = 0; kc < 8; kc++) {
            uint2 v0 = *(const uint2*)(hfb + ((kc * 4 + np * 2 + 0) * 32 + l) * 8);
            uint2 v1 = *(const uint2*)(hfb + ((kc * 4 + np * 2 + 1) * 32 + l) * 8);
            if (doG) {
              uint4 a = *(const uint4*)(sb + OFF_WN +
                         ((size_t)(jt * 8 + kc) * 32 + l) * 16);
              uint32_t An[4] = { a.x, a.y, a.z, a.w };
              mma16816(D[0][0], Ar[kc], v0.x, v0.y);
              mma16816(D[0][1], Ar[kc], v1.x, v1.y);
              mma16816(D[1][0], Az[kc], v0.x, v0.y);
              mma16816(D[1][1], Az[kc], v1.x, v1.y);
              mma16816(D[2][0], An, v0.x, v0.y);
              mma16816(D[2][1], An, v1.x, v1.y);
            }
            if (doH) {
              uint4 a = *(const uint4*)(sb + OFF_W1F +
                         ((size_t)(jt * 8 + kc) * 32 + l) * 16);
              uint32_t A1[4] = { a.x, a.y, a.z, a.w };
              mma16816(Da[0], A1, v0.x, v0.y);
              mma16816(Da[1], A1, v1.x, v1.y);
            }
          }
          if (doG) {
            #pragma unroll
            for (int g = 0; g < 3; g++)
              #pragma unroll
              for (int s = 0; s < 2; s++)
                #pragma unroll
                for (int rh = 0; rh < 2; rh++)
                  #pragma unroll
                  for (int cc = 0; cc < 2; cc++)
                    dgh[(g * 32 + (np * 2 + s) * 8 + tg * 2 + cc) * 132
                        + jt * 16 + rh * 8 + grp] = D[g][s][rh * 2 + cc];
          }
          if (doH) {
            #pragma unroll
            for (int s = 0; s < 2; s++)
              #pragma unroll
              for (int rh = 0; rh < 2; rh++)
                #pragma unroll
                for (int cc = 0; cc < 2; cc++)
                  ath[((np * 2 + s) * 8 + tg * 2 + cc) * 132
                      + jt * 16 + rh * 8 + grp] =
                      fmaxf(Da[s][rh * 2 + cc] + (rh ? b1B : b1A), 0.f);
          }
        }
        BARX(h + 1, NT);
      }
    }
  } else {
    // ================= C-warps =================
    const int c = tid - 256;              // 0..255
    const int jj = (c & 63) * 2, ng = c >> 6;   // 2 j's, 8 n's (ng*8..)
    float wg[3][2][6], brv[2], bzv[2], binv[2], bhnv[2];
    #pragma unroll
    for (int jp = 0; jp < 2; jp++) {
      int j = jj + jp;
      #pragma unroll
      for (int g = 0; g < 3; g++)
        #pragma unroll
        for (int i = 0; i < 6; i++)
          wg[g][jp][i] = w_ih[(size_t)(g * 128 + j) * 6 + i];
      brv[jp]  = b_ih[j] + b_hh[j];
      bzv[jp]  = b_ih[128 + j] + b_hh[128 + j];
      binv[jp] = b_ih[256 + j];
      bhnv[jp] = b_hh[256 + j];
    }
    float b2r = (c < 192) ? b2[c % 6] : 0.f;
    float hreg[2][8][2];
    #pragma unroll
    for (int h = 0; h < 2; h++)
      #pragma unroll
      for (int q = 0; q < 8; q++) { hreg[h][q][0] = 0.f; hreg[h][q][1] = 0.f; }
    const uint32_t sj = (uint32_t)((jj >> 4) * 128 + ((jj & 7) >> 1));
    const uint32_t bj = (uint32_t)(((jj >> 3) & 1) * 4);

    for (int t = 0; t <= 80; t++) {
      #pragma unroll 1
      for (int h = 0; h < 2; h++) {
        BARX(h + 1, NT);
        if (t > 50) {   // w2 epilogue for this half (32 rows x 6)
          if (c < 192) {
            int n = c / 6, i = c - n * 6;
            const float4* a4 = (const float4*)((float*)(sb + OFF_AT)
                                + h * 4224 + n * 132);
            const float4* wv = (const float4*)((float*)(sb + OFF_W2) + i * 128);
            float acc = b2r;
            #pragma unroll 8
            for (int k4 = 0; k4 < 32; k4++) {
              float4 a = a4[k4], ww = wv[k4];
              acc = fmaf(a.x, ww.x, fmaf(a.y, ww.y,
                    fmaf(a.z, ww.z, fmaf(a.w, ww.w, acc))));
            }
            ((float*)(sb + OFF_XSD))[h * 192 + c] = acc;
            out[(size_t)(row0 + h * 32 + n) * 180 + (size_t)(t - 51) * 6 + i] = acc;
          }
          BARX(3, 256);
        }
        if (t < 80) {   // gi + combine -> h_t written to HF
          const float* xq =
              (t < 50) ? (const float*)(sb + OFF_XSE) + (h * 2 + (t & 1)) * 192
            : (t == 50) ? (const float*)(sb + OFF_XSE) + (h * 2 + 1) * 192
            : (const float*)(sb + OFF_XSD) + h * 192;
          const float* dgh = (const float*)(sb + OFF_DG) + h * 12672;
          #pragma unroll
          for (int q = 0; q < 8; q++) {
            const int n = ng * 8 + q;
            const float* xp = xq + n * 6;
            float2 Dr = *(const float2*)(dgh + (0 * 32 + n) * 132 + jj);
            float2 Dz = *(const float2*)(dgh + (1 * 32 + n) * 132 + jj);
            float2 Dn = *(const float2*)(dgh + (2 * 32 + n) * 132 + jj);
            float x0 = xp[0], x1 = xp[1], x2 = xp[2],
                  x3 = xp[3], x4 = xp[4], x5 = xp[5];
            float hv[2];
            #pragma unroll
            for (int jp = 0; jp < 2; jp++) {
              float gr = brv[jp], gz = bzv[jp], gn = binv[jp];
              gr = fmaf(wg[0][jp][0], x0, fmaf(wg[0][jp][1], x1, fmaf(wg[0][jp][2], x2,
                   fmaf(wg[0][jp][3], x3, fmaf(wg[0][jp][4], x4, fmaf(wg[0][jp][5], x5, gr))))));
              gz = fmaf(wg[1][jp][0], x0, fmaf(wg[1][jp][1], x1, fmaf(wg[1][jp][2], x2,
                   fmaf(wg[1][jp][3], x3, fmaf(wg[1][jp][4], x4, fmaf(wg[1][jp][5], x5, gz))))));
              gn = fmaf(wg[2][jp][0], x0, fmaf(wg[2][jp][1], x1, fmaf(wg[2][jp][2], x2,
                   fmaf(wg[2][jp][3], x3, fmaf(wg[2][jp][4], x4, fmaf(wg[2][jp][5], x5, gn))))));
              float r = sigf(gr + (jp ? Dr.y : Dr.x));
              float z = sigf(gz + (jp ? Dz.y : Dz.x));
              float nn = tanhfast(fmaf(r, (jp ? Dn.y : Dn.x) + bhnv[jp], gn));
              float hh = fmaf(z, hreg[h][q][jp] - nn, nn);
              hreg[h][q][jp] = hh;
              hv[jp] = hh;
            }
            __half2 hi2(__float2half_rn(hv[0]), __float2half_rn(hv[1]));
            uint32_t slot = sj + (uint32_t)((n >> 3) * 32 + (n & 7) * 4);
            *(uint32_t*)(sb + OFF_HF + h * 8192 + slot * 8 + bj)
                = *(uint32_t*)&hi2;
          }
        }
        if (h == 1 && t + 1 < 50) {   // encoder x prefetch (384 values)
          #pragma unroll
          for (int idx = c; idx < 384; idx += 256) {
            int hh = idx / 192, rr = (idx % 192) / 6, i = idx % 6;
            ((float*)(sb + OFF_XSE))[(hh * 2 + ((t + 1) & 1)) * 192 + rr * 6 + i]
                = history[(size_t)(row0 + hh * 32 + rr) * 300
                          + (size_t)(t + 1) * 6 + i];
          }
        }
      }
    }
  }
}

extern "C" void kernel_launch(void* const* d_in, const int* in_sizes, int n_in,
                              void* d_out, int out_size) {
  const float* history = (const float*)d_in[0];
  const float* w_ih    = (const float*)d_in[1];
  const float* w_hh    = (const float*)d_in[2];
  const float* b_ih    = (const float*)d_in[3];
  const float* b_hh    = (const float*)d_in[4];
  const float* w1      = (const float*)d_in[5];
  const float* b1      = (const float*)d_in[6];
  const float* w2      = (const float*)d_in[7];
  const float* b2      = (const float*)d_in[8];
  float* out = (float*)d_out;

  cudaFuncSetAttribute(gru_r64_kernel,
                       cudaFuncAttributeMaxDynamicSharedMemorySize, SMEM_TOTAL);
  gru_r64_kernel<<<256, NT, SMEM_TOTAL>>>(
      history, w_ih, w_hh, b_ih, b_hh, w1, b1, w2, b2, out);
}

// round 16
// speedup vs baseline: 1.3252x; 1.1700x over previous
#include <cuda_runtime.h>
#include <cuda_fp16.h>
#include <cstdint>

// TrajectoryGRU: fully-fused fp16 mma. gi folded into GEMM over [h; x]
// (K=144 = 9 kchunks; chunk 8 carries x). n-gate keeps separate h/x
// accumulators for r*(.) semantics. No M/C split: 16 warps, each owns
// (jt, n-half), register-resident combine, double-buffered HF ->
// 1 barrier per encoder step. ROWS=64/CTA, grid 256 (2 waves).

#define NT 512
#define OFF_WA  0        // A-frags [jt8][g3][kc9][l32] u4 = 110592
#define OFF_W1F 110592   // w1 frags [jt8][kc8][l32] u4 = 32768
#define OFF_HF  143360   // [p2][(kc9*nt8)=72][l32] u2 = 36864
#define OFF_AT  180224   // [64][132] f32 = 33792
#define OFF_W2  214016   // [6][128] f32 = 3072
#define SMEM_TOTAL 217088
#define HFSTRIDE 18432

__device__ __forceinline__ void mma16816(float* d, const uint32_t* a,
                                         uint32_t b0, uint32_t b1) {
  asm volatile(
    "mma.sync.aligned.m16n8k16.row.col.f32.f16.f16.f32 "
    "{%0,%1,%2,%3}, {%4,%5,%6,%7}, {%8,%9}, {%0,%1,%2,%3};"
    : "+f"(d[0]), "+f"(d[1]), "+f"(d[2]), "+f"(d[3])
    : "r"(a[0]), "r"(a[1]), "r"(a[2]), "r"(a[3]), "r"(b0), "r"(b1));
}
__device__ __forceinline__ uint32_t packh2(float x, float y) {
  __half2 p(__float2half_rn(x), __float2half_rn(y));
  return *reinterpret_cast<uint32_t*>(&p);
}
__device__ __forceinline__ float sigf(float v) {
  return __fdividef(1.0f, 1.0f + __expf(-v));
}
__device__ __forceinline__ float tanhfast(float v) {
  float av = fabsf(v), e = __expf(-2.0f * av);
  return copysignf(__fdividef(1.0f - e, 1.0f + e), v);
}
// x-slot byte offset within an HF buffer (kc=8 rows 0..5)
__device__ __forceinline__ uint32_t hfx(int n, int i) {
  return (uint32_t)(((64 + (n >> 3)) * 32 + (n & 7) * 4 + (i >> 1)) * 8
                    + (i & 1) * 2);
}

__global__ void __launch_bounds__(NT, 1)
gru_fuse_kernel(const float* __restrict__ history, const float* __restrict__ w_ih,
                const float* __restrict__ w_hh, const float* __restrict__ b_ih,
                const float* __restrict__ b_hh, const float* __restrict__ w1,
                const float* __restrict__ b1, const float* __restrict__ w2,
                const float* __restrict__ b2, float* __restrict__ out)
{
  extern __shared__ char sb[];
  const int tid = threadIdx.x, w = tid >> 5, l = tid & 31;
  const int grp = l >> 2, tg = l & 3;
  const int jt = w >> 1, nh = w & 1;
  const int row0 = blockIdx.x * 64;

  // ---------- init: A-fragments (W_hh kc0-7, W_ih kc8) ----------
  for (int idx = tid; idx < 6912; idx += NT) {
    int ll = idx & 31, kc = (idx >> 5) % 9, g = (idx / 288) % 3, jq = idx / 864;
    int jA = jq * 16 + (ll >> 2), jB = jA + 8, k0 = (ll & 3) * 2;
    uint4 f;
    if (kc < 8) {
      const float* ba = w_hh + (size_t)(g * 128 + jA) * 128 + kc * 16;
      const float* bb = w_hh + (size_t)(g * 128 + jB) * 128 + kc * 16;
      f.x = packh2(ba[k0], ba[k0 + 1]);
      f.y = packh2(bb[k0], bb[k0 + 1]);
      f.z = packh2(ba[k0 + 8], ba[k0 + 9]);
      f.w = packh2(bb[k0 + 8], bb[k0 + 9]);
    } else {
      const float* ia = w_ih + (size_t)(g * 128 + jA) * 6;
      const float* ib = w_ih + (size_t)(g * 128 + jB) * 6;
      float a0 = (k0 < 6) ? ia[k0] : 0.f, a1 = (k0 + 1 < 6) ? ia[k0 + 1] : 0.f;
      float b0 = (k0 < 6) ? ib[k0] : 0.f, b1v = (k0 + 1 < 6) ? ib[k0 + 1] : 0.f;
      f.x = packh2(a0, a1);
      f.y = packh2(b0, b1v);
      f.z = packh2(0.f, 0.f);
      f.w = packh2(0.f, 0.f);
    }
    *(uint4*)(sb + OFF_WA + (size_t)idx * 16) = f;
  }
  for (int idx = tid; idx < 2048; idx += NT) {   // w1 frags
    int ll = idx & 31, kc = (idx >> 5) & 7, jq = idx >> 8;
    int jA = jq * 16 + (ll >> 2), jB = jA + 8, k0 = kc * 16 + (ll & 3) * 2;
    const float* ra = w1 + (size_t)jA * 128;
    const float* rb = w1 + (size_t)jB * 128;
    uint4 f = { packh2(ra[k0], ra[k0 + 1]),   packh2(rb[k0], rb[k0 + 1]),
                packh2(ra[k0 + 8], ra[k0 + 9]), packh2(rb[k0 + 8], rb[k0 + 9]) };
    *(uint4*)(sb + OFF_W1F + (size_t)idx * 16) = f;
  }
  for (int i = tid; i < 9216; i += NT) ((uint32_t*)(sb + OFF_HF))[i] = 0u;
  for (int i = tid; i < 768; i += NT) ((float*)(sb + OFF_W2))[i] = w2[i];
  __syncthreads();
  if (tid < 384) {   // x_0 into HF[0] kc8
    int n = tid / 6, i = tid - (tid / 6) * 6;
    float v = history[(size_t)(row0 + n) * 300 + i];
    *(__half*)(sb + OFF_HF + hfx(n, i)) = __float2half_rn(v);
  }

  // ---------- per-lane constants ----------
  const int jA = jt * 16 + grp, jB = jA + 8;
  const float brA = b_ih[jA] + b_hh[jA],           brB = b_ih[jB] + b_hh[jB];
  const float bzA = b_ih[128 + jA] + b_hh[128 + jA], bzB = b_ih[128 + jB] + b_hh[128 + jB];
  const float binA = b_ih[256 + jA],               binB = b_ih[256 + jB];
  const float bhnA = b_hh[256 + jA],               bhnB = b_hh[256 + jB];
  const float b1A = b1[jA], b1B = b1[jB];
  float b2r = (tid < 384) ? b2[tid % 6] : 0.f;
  float hreg[16];
  #pragma unroll
  for (int e = 0; e < 16; e++) hreg[e] = 0.f;
  float* at = (float*)(sb + OFF_AT);
  __syncthreads();

  int p = 0;
  for (int t = 0; t <= 80; t++, p ^= 1) {
    char* hfb = sb + OFF_HF + p * HFSTRIDE;
    char* hfn = sb + OFF_HF + (p ^ 1) * HFSTRIDE;

    if (t >= 51) {   // decoder head: x_t = head(h_t), h_t in HF[p]
      float Da[4][4];
      #pragma unroll
      for (int nt = 0; nt < 4; nt++)
        #pragma unroll
        for (int r = 0; r < 4; r++) Da[nt][r] = 0.f;
      #pragma unroll
      for (int kc = 0; kc < 8; kc++) {
        uint4 a = *(const uint4*)(sb + OFF_W1F +
                    ((size_t)(jt * 8 + kc) * 32 + l) * 16);
        uint32_t A[4] = { a.x, a.y, a.z, a.w };
        #pragma unroll
        for (int nt = 0; nt < 4; nt++) {
          uint2 v = *(const uint2*)(hfb + ((kc * 8 + nh * 4 + nt) * 32 + l) * 8);
          mma16816(Da[nt], A, v.x, v.y);
        }
      }
      #pragma unroll
      for (int nt = 0; nt < 4; nt++)
        #pragma unroll
        for (int rh = 0; rh < 2; rh++)
          #pragma unroll
          for (int cc = 0; cc < 2; cc++)
            at[(nh * 32 + nt * 8 + tg * 2 + cc) * 132 + jt * 16 + rh * 8 + grp]
                = fmaxf(Da[nt][rh * 2 + cc] + (rh ? b1B : b1A), 0.f);
      __syncthreads();
      if (tid < 384) {   // w2 -> prediction + x_t into HF[p] kc8
        int n = tid / 6, i = tid - n * 6;
        const float4* a4 = (const float4*)(at + n * 132);
        const float4* wv = (const float4*)((float*)(sb + OFF_W2) + i * 128);
        float acc = b2r;
        #pragma unroll 8
        for (int k4 = 0; k4 < 32; k4++) {
          float4 a = a4[k4], ww = wv[k4];
          acc = fmaf(a.x, ww.x, fmaf(a.y, ww.y,
                fmaf(a.z, ww.z, fmaf(a.w, ww.w, acc))));
        }
        out[(size_t)(row0 + n) * 180 + (size_t)(t - 51) * 6 + i] = acc;
        if (t < 80)
          *(__half*)(hfb + hfx(n, i)) = __float2half_rn(acc);
      }
      __syncthreads();
    }

    if (t < 80) {
      // ---- fused gate GEMM over [h; x] : 9 kchunks ----
      float Dr[4][4], Dz[4][4], Dnh[4][4], Dnx[4][4];
      #pragma unroll
      for (int nt = 0; nt < 4; nt++)
        #pragma unroll
        for (int r = 0; r < 4; r++) {
          Dr[nt][r] = 0.f; Dz[nt][r] = 0.f; Dnh[nt][r] = 0.f; Dnx[nt][r] = 0.f;
        }
      #pragma unroll
      for (int kc = 0; kc < 9; kc++) {
        uint2 v[4];
        #pragma unroll
        for (int nt = 0; nt < 4; nt++)
          v[nt] = *(const uint2*)(hfb + ((kc * 8 + nh * 4 + nt) * 32 + l) * 8);
        uint4 ar = *(const uint4*)(sb + OFF_WA +
                    ((size_t)((jt * 3 + 0) * 9 + kc) * 32 + l) * 16);
        uint4 az = *(const uint4*)(sb + OFF_WA +
                    ((size_t)((jt * 3 + 1) * 9 + kc) * 32 + l) * 16);
        uint4 an = *(const uint4*)(sb + OFF_WA +
                    ((size_t)((jt * 3 + 2) * 9 + kc) * 32 + l) * 16);
        uint32_t Ar[4] = { ar.x, ar.y, ar.z, ar.w };
        uint32_t Az[4] = { az.x, az.y, az.z, az.w };
        uint32_t An[4] = { an.x, an.y, an.z, an.w };
        #pragma unroll
        for (int nt = 0; nt < 4; nt++) {
          mma16816(Dr[nt], Ar, v[nt].x, v[nt].y);
          mma16816(Dz[nt], Az, v[nt].x, v[nt].y);
        }
        if (kc < 8) {
          #pragma unroll
          for (int nt = 0; nt < 4; nt++)
            mma16816(Dnh[nt], An, v[nt].x, v[nt].y);
        } else {
          #pragma unroll
          for (int nt = 0; nt < 4; nt++)
            mma16816(Dnx[nt], An, v[nt].x, v[nt].y);
        }
      }
      // ---- register-resident combine -> h_{t+1} into HF[p^1] ----
      #pragma unroll
      for (int nt = 0; nt < 4; nt++)
        #pragma unroll
        for (int rh = 0; rh < 2; rh++)
          #pragma unroll
          for (int cc = 0; cc < 2; cc++) {
            const int e = rh * 2 + cc, hi = nt * 4 + e;
            float r = sigf(Dr[nt][e] + (rh ? brB : brA));
            float z = sigf(Dz[nt][e] + (rh ? bzB : bzA));
            float nn = tanhfast(fmaf(r, Dnh[nt][e] + (rh ? bhnB : bhnA),
                                     Dnx[nt][e] + (rh ? binB : binA)));
            float hv = fmaf(z, hreg[hi] - nn, nn);
            hreg[hi] = hv;
            uint32_t off = (uint32_t)(((jt * 8 + nh * 4 + nt) * 32
                          + (tg * 2 + cc) * 4 + (grp >> 1)) * 8
                          + rh * 4 + (grp & 1) * 2);
            *(__half*)(hfn + off) = __float2half_rn(hv);
          }
      // ---- encoder x prefetch into HF[p^1] kc8 ----
      if (t < 50 && tid < 384) {
        int tl = (t + 1 > 49) ? 49 : t + 1;
        int n = tid / 6, i = tid - (tid / 6) * 6;
        float v = history[(size_t)(row0 + n) * 300 + (size_t)tl * 6 + i];
        *(__half*)(hfn + hfx(n, i)) = __float2half_rn(v);
      }
      __syncthreads();
    }
  }
}

extern "C" void kernel_launch(void* const* d_in, const int* in_sizes, int n_in,
                              void* d_out, int out_size) {
  const float* history = (const float*)d_in[0];
  const float* w_ih    = (const float*)d_in[1];
  const float* w_hh    = (const float*)d_in[2];
  const float* b_ih    = (const float*)d_in[3];
  const float* b_hh    = (const float*)d_in[4];
  const float* w1      = (const float*)d_in[5];
  const float* b1      = (const float*)d_in[6];
  const float* w2      = (const float*)d_in[7];
  const float* b2      = (const float*)d_in[8];
  float* out = (float*)d_out;

  cudaFuncSetAttribute(gru_fuse_kernel,
                       cudaFuncAttributeMaxDynamicSharedMemorySize, SMEM_TOTAL);
  gru_fuse_kernel<<<256, NT, SMEM_TOTAL>>>(
      history, w_ih, w_hh, b_ih, b_hh, w1, b1, w2, b2, out);
}

// round 17
// speedup vs baseline: 1.4233x; 1.0740x over previous
#include <cuda_runtime.h>
#include <cuda_fp16.h>
#include <cstdint>

// TrajectoryGRU: fully-fused fp16 mma (R16 structure) + HW tanh.approx
// activations (1 MUFU each; sigmoid via 0.5*tanh(v/2)+0.5).
// gi folded into GEMM over [h; x] (K=144 = 9 kchunks; chunk 8 = x).
// 16 warps, each owns (jt, n-half), register-resident combine,
// double-buffered HF, 1 barrier/encoder step. ROWS=64/CTA, grid 256.

#define NT 512
#define OFF_WA  0        // A-frags [jt8][g3][kc9][l32] u4 = 110592
#define OFF_W1F 110592   // w1 frags [jt8][kc8][l32] u4 = 32768
#define OFF_HF  143360   // [p2][(kc9*nt8)=72][l32] u2 = 36864
#define OFF_AT  180224   // [64][132] f32 = 33792
#define OFF_W2  214016   // [6][128] f32 = 3072
#define SMEM_TOTAL 217088
#define HFSTRIDE 18432

__device__ __forceinline__ void mma16816(float* d, const uint32_t* a,
                                         uint32_t b0, uint32_t b1) {
  asm volatile(
    "mma.sync.aligned.m16n8k16.row.col.f32.f16.f16.f32 "
    "{%0,%1,%2,%3}, {%4,%5,%6,%7}, {%8,%9}, {%0,%1,%2,%3};"
    : "+f"(d[0]), "+f"(d[1]), "+f"(d[2]), "+f"(d[3])
    : "r"(a[0]), "r"(a[1]), "r"(a[2]), "r"(a[3]), "r"(b0), "r"(b1));
}
__device__ __forceinline__ uint32_t packh2(float x, float y) {
  __half2 p(__float2half_rn(x), __float2half_rn(y));
  return *reinterpret_cast<uint32_t*>(&p);
}
__device__ __forceinline__ float tanhapx(float v) {
  float r;
  asm("tanh.approx.f32 %0, %1;" : "=f"(r) : "f"(v));
  return r;
}
__device__ __forceinline__ float sigapx(float v) {
  return fmaf(0.5f, tanhapx(0.5f * v), 0.5f);
}
// x-slot byte offset within an HF buffer (kc=8 rows 0..5)
__device__ __forceinline__ uint32_t hfx(int n, int i) {
  return (uint32_t)(((64 + (n >> 3)) * 32 + (n & 7) * 4 + (i >> 1)) * 8
                    + (i & 1) * 2);
}

__global__ void __launch_bounds__(NT, 1)
gru_fuse2_kernel(const float* __restrict__ history, const float* __restrict__ w_ih,
                 const float* __restrict__ w_hh, const float* __restrict__ b_ih,
                 const float* __restrict__ b_hh, const float* __restrict__ w1,
                 const float* __restrict__ b1, const float* __restrict__ w2,
                 const float* __restrict__ b2, float* __restrict__ out)
{
  extern __shared__ char sb[];
  const int tid = threadIdx.x, w = tid >> 5, l = tid & 31;
  const int grp = l >> 2, tg = l & 3;
  const int jt = w >> 1, nh = w & 1;
  const int row0 = blockIdx.x * 64;

  // ---------- init: A-fragments (W_hh kc0-7, W_ih kc8) ----------
  for (int idx = tid; idx < 6912; idx += NT) {
    int ll = idx & 31, kc = (idx >> 5) % 9, g = (idx / 288) % 3, jq = idx / 864;
    int jA = jq * 16 + (ll >> 2), jB = jA + 8, k0 = (ll & 3) * 2;
    uint4 f;
    if (kc < 8) {
      const float* ba = w_hh + (size_t)(g * 128 + jA) * 128 + kc * 16;
      const float* bb = w_hh + (size_t)(g * 128 + jB) * 128 + kc * 16;
      f.x = packh2(ba[k0], ba[k0 + 1]);
      f.y = packh2(bb[k0], bb[k0 + 1]);
      f.z = packh2(ba[k0 + 8], ba[k0 + 9]);
      f.w = packh2(bb[k0 + 8], bb[k0 + 9]);
    } else {
      const float* ia = w_ih + (size_t)(g * 128 + jA) * 6;
      const float* ib = w_ih + (size_t)(g * 128 + jB) * 6;
      float a0 = (k0 < 6) ? ia[k0] : 0.f, a1 = (k0 + 1 < 6) ? ia[k0 + 1] : 0.f;
      float b0 = (k0 < 6) ? ib[k0] : 0.f, b1v = (k0 + 1 < 6) ? ib[k0 + 1] : 0.f;
      f.x = packh2(a0, a1);
      f.y = packh2(b0, b1v);
      f.z = packh2(0.f, 0.f);
      f.w = packh2(0.f, 0.f);
    }
    *(uint4*)(sb + OFF_WA + (size_t)idx * 16) = f;
  }
  for (int idx = tid; idx < 2048; idx += NT) {   // w1 frags
    int ll = idx & 31, kc = (idx >> 5) & 7, jq = idx >> 8;
    int jA = jq * 16 + (ll >> 2), jB = jA + 8, k0 = kc * 16 + (ll & 3) * 2;
    const float* ra = w1 + (size_t)jA * 128;
    const float* rb = w1 + (size_t)jB * 128;
    uint4 f = { packh2(ra[k0], ra[k0 + 1]),   packh2(rb[k0], rb[k0 + 1]),
                packh2(ra[k0 + 8], ra[k0 + 9]), packh2(rb[k0 + 8], rb[k0 + 9]) };
    *(uint4*)(sb + OFF_W1F + (size_t)idx * 16) = f;
  }
  for (int i = tid; i < 9216; i += NT) ((uint32_t*)(sb + OFF_HF))[i] = 0u;
  for (int i = tid; i < 768; i += NT) ((float*)(sb + OFF_W2))[i] = w2[i];
  __syncthreads();
  if (tid < 384) {   // x_0 into HF[0] kc8
    int n = tid / 6, i = tid - (tid / 6) * 6;
    float v = history[(size_t)(row0 + n) * 300 + i];
    *(__half*)(sb + OFF_HF + hfx(n, i)) = __float2half_rn(v);
  }

  // ---------- per-lane constants ----------
  const int jA = jt * 16 + grp, jB = jA + 8;
  const float brA = b_ih[jA] + b_hh[jA],             brB = b_ih[jB] + b_hh[jB];
  const float bzA = b_ih[128 + jA] + b_hh[128 + jA], bzB = b_ih[128 + jB] + b_hh[128 + jB];
  const float binA = b_ih[256 + jA],                 binB = b_ih[256 + jB];
  const float bhnA = b_hh[256 + jA],                 bhnB = b_hh[256 + jB];
  const float b1A = b1[jA], b1B = b1[jB];
  float b2r = (tid < 384) ? b2[tid % 6] : 0.f;
  float hreg[16];
  #pragma unroll
  for (int e = 0; e < 16; e++) hreg[e] = 0.f;
  float* at = (float*)(sb + OFF_AT);
  __syncthreads();

  int p = 0;
  for (int t = 0; t <= 80; t++, p ^= 1) {
    char* hfb = sb + OFF_HF + p * HFSTRIDE;
    char* hfn = sb + OFF_HF + (p ^ 1) * HFSTRIDE;

    if (t >= 51) {   // decoder head: x_t = head(h_t), h_t in HF[p]
      float Da[4][4];
      #pragma unroll
      for (int nt = 0; nt < 4; nt++)
        #pragma unroll
        for (int r = 0; r < 4; r++) Da[nt][r] = 0.f;
      #pragma unroll
      for (int kc = 0; kc < 8; kc++) {
        uint4 a = *(const uint4*)(sb + OFF_W1F +
                    ((size_t)(jt * 8 + kc) * 32 + l) * 16);
        uint32_t A[4] = { a.x, a.y, a.z, a.w };
        #pragma unroll
        for (int nt = 0; nt < 4; nt++) {
          uint2 v = *(const uint2*)(hfb + ((kc * 8 + nh * 4 + nt) * 32 + l) * 8);
          mma16816(Da[nt], A, v.x, v.y);
        }
      }
      #pragma unroll
      for (int nt = 0; nt < 4; nt++)
        #pragma unroll
        for (int rh = 0; rh < 2; rh++)
          #pragma unroll
          for (int cc = 0; cc < 2; cc++)
            at[(nh * 32 + nt * 8 + tg * 2 + cc) * 132 + jt * 16 + rh * 8 + grp]
                = fmaxf(Da[nt][rh * 2 + cc] + (rh ? b1B : b1A), 0.f);
      __syncthreads();
      if (tid < 384) {   // w2 -> prediction + x_t into HF[p] kc8
        int n = tid / 6, i = tid - n * 6;
        const float4* a4 = (const float4*)(at + n * 132);
        const float4* wv = (const float4*)((float*)(sb + OFF_W2) + i * 128);
        float acc = b2r;
        #pragma unroll 8
        for (int k4 = 0; k4 < 32; k4++) {
          float4 a = a4[k4], ww = wv[k4];
          acc = fmaf(a.x, ww.x, fmaf(a.y, ww.y,
                fmaf(a.z, ww.z, fmaf(a.w, ww.w, acc))));
        }
        out[(size_t)(row0 + n) * 180 + (size_t)(t - 51) * 6 + i] = acc;
        if (t < 80)
          *(__half*)(hfb + hfx(n, i)) = __float2half_rn(acc);
      }
      __syncthreads();
    }

    if (t < 80) {
      // ---- fused gate GEMM over [h; x] : 9 kchunks ----
      float Dr[4][4], Dz[4][4], Dnh[4][4], Dnx[4][4];
      #pragma unroll
      for (int nt = 0; nt < 4; nt++)
        #pragma unroll
        for (int r = 0; r < 4; r++) {
          Dr[nt][r] = 0.f; Dz[nt][r] = 0.f; Dnh[nt][r] = 0.f; Dnx[nt][r] = 0.f;
        }
      #pragma unroll
      for (int kc = 0; kc < 9; kc++) {
        uint2 v[4];
        #pragma unroll
        for (int nt = 0; nt < 4; nt++)
          v[nt] = *(const uint2*)(hfb + ((kc * 8 + nh * 4 + nt) * 32 + l) * 8);
        uint4 ar = *(const uint4*)(sb + OFF_WA +
                    ((size_t)((jt * 3 + 0) * 9 + kc) * 32 + l) * 16);
        uint4 az = *(const uint4*)(sb + OFF_WA +
                    ((size_t)((jt * 3 + 1) * 9 + kc) * 32 + l) * 16);
        uint4 an = *(const uint4*)(sb + OFF_WA +
                    ((size_t)((jt * 3 + 2) * 9 + kc) * 32 + l) * 16);
        uint32_t Ar[4] = { ar.x, ar.y, ar.z, ar.w };
        uint32_t Az[4] = { az.x, az.y, az.z, az.w };
        uint32_t An[4] = { an.x, an.y, an.z, an.w };
        #pragma unroll
        for (int nt = 0; nt < 4; nt++) {
          mma16816(Dr[nt], Ar, v[nt].x, v[nt].y);
          mma16816(Dz[nt], Az, v[nt].x, v[nt].y);
        }
        if (kc < 8) {
          #pragma unroll
          for (int nt = 0; nt < 4; nt++)
            mma16816(Dnh[nt], An, v[nt].x, v[nt].y);
        } else {
          #pragma unroll
          for (int nt = 0; nt < 4; nt++)
            mma16816(Dnx[nt], An, v[nt].x, v[nt].y);
        }
      }
      // ---- register-resident combine -> h_{t+1} into HF[p^1] ----
      #pragma unroll
      for (int nt = 0; nt < 4; nt++)
        #pragma unroll
        for (int rh = 0; rh < 2; rh++)
          #pragma unroll
          for (int cc = 0; cc < 2; cc++) {
            const int e = rh * 2 + cc, hi = nt * 4 + e;
            float r = sigapx(Dr[nt][e] + (rh ? brB : brA));
            float z = sigapx(Dz[nt][e] + (rh ? bzB : bzA));
            float nn = tanhapx(fmaf(r, Dnh[nt][e] + (rh ? bhnB : bhnA),
                                    Dnx[nt][e] + (rh ? binB : binA)));
            float hv = fmaf(z, hreg[hi] - nn, nn);
            hreg[hi] = hv;
            uint32_t off = (uint32_t)(((jt * 8 + nh * 4 + nt) * 32
                          + (tg * 2 + cc) * 4 + (grp >> 1)) * 8
                          + rh * 4 + (grp & 1) * 2);
            *(__half*)(hfn + off) = __float2half_rn(hv);
          }
      // ---- encoder x prefetch into HF[p^1] kc8 ----
      if (t < 50 && tid < 384) {
        int tl = (t + 1 > 49) ? 49 : t + 1;
        int n = tid / 6, i = tid - (tid / 6) * 6;
        float v = history[(size_t)(row0 + n) * 300 + (size_t)tl * 6 + i];
        *(__half*)(hfn + hfx(n, i)) = __float2half_rn(v);
      }
      __syncthreads();
    }
  }
}

extern "C" void kernel_launch(void* const* d_in, const int* in_sizes, int n_in,
                              void* d_out, int out_size) {
  const float* history = (const float*)d_in[0];
  const float* w_ih    = (const float*)d_in[1];
  const float* w_hh    = (const float*)d_in[2];
  const float* b_ih    = (const float*)d_in[3];
  const float* b_hh    = (const float*)d_in[4];
  const float* w1      = (const float*)d_in[5];
  const float* b1      = (const float*)d_in[6];
  const float* w2      = (const float*)d_in[7];
  const float* b2      = (const float*)d_in[8];
  float* out = (float*)d_out;

  cudaFuncSetAttribute(gru_fuse2_kernel,
                       cudaFuncAttributeMaxDynamicSharedMemorySize, SMEM_TOTAL);
  gru_fuse2_kernel<<<256, NT, SMEM_TOTAL>>>(
      history, w_ih, w_hh, b_ih, b_hh, w1, b1, w2, b2, out);
}